// round 16
// baseline (speedup 1.0000x reference)
#include <cuda_runtime.h>
#include <cuda_bf16.h>
#include <cstdint>

#define N_NODES 50000
#define N_EDGES 400000
#define E_TOT   (N_EDGES + N_NODES)
#define HEADS   4
#define HID     64
#define HC      256     // HEADS*HID
#define LAT     32
#define IN_DIM  128
#define NGRAPH  64
#define NCLS    10
#define NEG_SLOPE 0.2f

// ---------------- static scratch (no allocations allowed) ----------------
__device__ float    g_xl[(size_t)N_NODES * HC];
__device__ float    g_xr[(size_t)N_NODES * HC];
__device__ float    g_h[(size_t)N_NODES * HID];
__device__ int      g_deg[N_NODES];
__device__ int      g_cursor[N_NODES];
__device__ int      g_rs[N_NODES + 1];               // CSR row starts
__device__ int      g_csr_src[E_TOT];                // src node per CSR slot
__device__ float4   g_cea[E_TOT];                    // edge attr per CSR slot (w unused)
__device__ float    g_easum[3];
__device__ float    g_gemb[NGRAPH * LAT];

__device__ __forceinline__ float warp_sum(float v) {
    #pragma unroll
    for (int o = 16; o > 0; o >>= 1) v += __shfl_xor_sync(0xFFFFFFFFu, v, o);
    return v;
}

// ---------------- edge-attr mean (sums; divided on use) ----------------
__global__ void ea_sum_kernel(const float* __restrict__ ea) {
    float s0 = 0.f, s1 = 0.f, s2 = 0.f;
    for (int i = blockIdx.x * blockDim.x + threadIdx.x; i < N_EDGES;
         i += gridDim.x * blockDim.x) {
        s0 += ea[i * 3 + 0];
        s1 += ea[i * 3 + 1];
        s2 += ea[i * 3 + 2];
    }
    s0 = warp_sum(s0); s1 = warp_sum(s1); s2 = warp_sum(s2);
    if ((threadIdx.x & 31) == 0) {
        atomicAdd(&g_easum[0], s0);
        atomicAdd(&g_easum[1], s1);
        atomicAdd(&g_easum[2], s2);
    }
}

// ---------------- CSR build ----------------
__global__ void count_kernel(const int* __restrict__ ei) {
    int e = blockIdx.x * blockDim.x + threadIdx.x;
    if (e >= E_TOT) return;
    int d = (e < N_EDGES) ? ei[N_EDGES + e] : (e - N_EDGES);
    atomicAdd(&g_deg[d], 1);
}

__global__ void scan_kernel() {
    __shared__ int part[256];
    const int CH = (N_NODES + 255) / 256;
    const int t = threadIdx.x;
    const int start = t * CH;
    int s = 0;
    for (int i = 0; i < CH; i++) {
        int n = start + i;
        if (n < N_NODES) s += g_deg[n];
    }
    part[t] = s;
    __syncthreads();
    for (int o = 1; o < 256; o <<= 1) {
        int u = (t >= o) ? part[t - o] : 0;
        __syncthreads();
        part[t] += u;
        __syncthreads();
    }
    int run = part[t] - s;
    for (int i = 0; i < CH; i++) {
        int n = start + i;
        if (n < N_NODES) { g_rs[n] = run; run += g_deg[n]; }
    }
    if (t == 255) g_rs[N_NODES] = run;
}

__global__ void scatter_kernel(const int* __restrict__ ei, const float* __restrict__ ea) {
    int e = blockIdx.x * blockDim.x + threadIdx.x;
    if (e >= E_TOT) return;
    int s, d;
    float4 c;
    if (e < N_EDGES) {
        s = ei[e]; d = ei[N_EDGES + e];
        c = make_float4(ea[e * 3 + 0], ea[e * 3 + 1], ea[e * 3 + 2], 0.f);
    } else {
        s = d = e - N_EDGES;
        const float inv = 1.0f / (float)N_EDGES;
        c = make_float4(g_easum[0] * inv, g_easum[1] * inv, g_easum[2] * inv, 0.f);
    }
    int pos = g_rs[d] + atomicAdd(&g_cursor[d], 1);
    g_csr_src[pos] = s;
    g_cea[pos] = c;
}

// ---------------- SGEMM: C[N,M] = A[N,K] @ W[K,M] (+bias, +relu) ----------------
// 128x128x8 tile, 256 threads, 8x8 microtile, double-buffered smem.
__global__ __launch_bounds__(256, 2)
void gemm_kernel(const float* __restrict__ A, const float* __restrict__ W,
                 const float* __restrict__ bias, float* __restrict__ C,
                 int N, int K, int M, int relu_flag) {
    __shared__ float As[2][8][132];
    __shared__ float Bs[2][8][128];
    const int tid = threadIdx.x;
    const int tx = tid & 15;
    const int ty = tid >> 4;
    const int row0 = blockIdx.y * 128;
    const int col0 = blockIdx.x * 128;
    const int ar  = tid >> 1;
    const int ac  = (tid & 1) * 4;
    const int agr = row0 + ar;

    float acc[8][8];
    #pragma unroll
    for (int i = 0; i < 8; i++)
        #pragma unroll
        for (int j = 0; j < 8; j++) acc[i][j] = 0.f;

    {
        float4 v = make_float4(0.f, 0.f, 0.f, 0.f);
        if (agr < N) v = *(const float4*)(A + (size_t)agr * K + ac);
        As[0][ac + 0][ar] = v.x; As[0][ac + 1][ar] = v.y;
        As[0][ac + 2][ar] = v.z; As[0][ac + 3][ar] = v.w;
        #pragma unroll
        for (int i = 0; i < 4; i++) {
            int idx = tid + i * 256;
            int r = idx >> 7, c = idx & 127;
            int gc = col0 + c;
            Bs[0][r][c] = (gc < M) ? W[(size_t)r * M + gc] : 0.f;
        }
    }
    __syncthreads();

    const int T = K >> 3;
    for (int kt = 0; kt < T; kt++) {
        const int cur = kt & 1, nxt = cur ^ 1;
        float4 av;
        float bv[4];
        const bool pre = (kt + 1 < T);
        if (pre) {
            const int k0 = (kt + 1) * 8;
            av = make_float4(0.f, 0.f, 0.f, 0.f);
            if (agr < N) av = *(const float4*)(A + (size_t)agr * K + k0 + ac);
            #pragma unroll
            for (int i = 0; i < 4; i++) {
                int idx = tid + i * 256;
                int r = idx >> 7, c = idx & 127;
                int gc = col0 + c;
                bv[i] = (gc < M) ? W[(size_t)(k0 + r) * M + gc] : 0.f;
            }
        }
        #pragma unroll
        for (int k = 0; k < 8; k++) {
            float a[8], b[8];
            *(float4*)(a)     = *(const float4*)&As[cur][k][ty * 8];
            *(float4*)(a + 4) = *(const float4*)&As[cur][k][ty * 8 + 4];
            *(float4*)(b)     = *(const float4*)&Bs[cur][k][tx * 8];
            *(float4*)(b + 4) = *(const float4*)&Bs[cur][k][tx * 8 + 4];
            #pragma unroll
            for (int i = 0; i < 8; i++)
                #pragma unroll
                for (int j = 0; j < 8; j++)
                    acc[i][j] = fmaf(a[i], b[j], acc[i][j]);
        }
        if (pre) {
            As[nxt][ac + 0][ar] = av.x; As[nxt][ac + 1][ar] = av.y;
            As[nxt][ac + 2][ar] = av.z; As[nxt][ac + 3][ar] = av.w;
            #pragma unroll
            for (int i = 0; i < 4; i++) {
                int idx = tid + i * 256;
                int r = idx >> 7, c = idx & 127;
                Bs[nxt][r][c] = bv[i];
            }
            __syncthreads();
        }
    }

    #pragma unroll
    for (int i = 0; i < 8; i++) {
        int gr = row0 + ty * 8 + i;
        if (gr >= N) continue;
        #pragma unroll
        for (int j = 0; j < 8; j++) {
            int gc = col0 + tx * 8 + j;
            if (gc >= M) continue;
            float v = acc[i][j];
            if (bias) v += bias[gc];
            if (relu_flag) v = fmaxf(v, 0.f);
            C[(size_t)gr * M + gc] = v;
        }
    }
}

// ---------------- fused dual SGEMM: xl = A@Wl, xr = A@Wr (M=HC=256 each) ----------------
// grid.x = 4: blocks 0-1 -> Wl/Cl cols 0-255, blocks 2-3 -> Wr/Cr cols 0-255.
__global__ __launch_bounds__(256, 2)
void gemm2_kernel(const float* __restrict__ A,
                  const float* __restrict__ Wl, const float* __restrict__ Wr,
                  float* __restrict__ Cl, float* __restrict__ Cr,
                  int N, int K) {
    __shared__ float As[2][8][132];
    __shared__ float Bs[2][8][128];
    const int tid = threadIdx.x;
    const int tx = tid & 15;
    const int ty = tid >> 4;
    const int bx = blockIdx.x;
    const float* W = (bx < 2) ? Wl : Wr;
    float* C       = (bx < 2) ? Cl : Cr;
    const int col0 = (bx & 1) * 128;
    const int row0 = blockIdx.y * 128;
    const int ar  = tid >> 1;
    const int ac  = (tid & 1) * 4;
    const int agr = row0 + ar;

    float acc[8][8];
    #pragma unroll
    for (int i = 0; i < 8; i++)
        #pragma unroll
        for (int j = 0; j < 8; j++) acc[i][j] = 0.f;

    {
        float4 v = make_float4(0.f, 0.f, 0.f, 0.f);
        if (agr < N) v = *(const float4*)(A + (size_t)agr * K + ac);
        As[0][ac + 0][ar] = v.x; As[0][ac + 1][ar] = v.y;
        As[0][ac + 2][ar] = v.z; As[0][ac + 3][ar] = v.w;
        #pragma unroll
        for (int i = 0; i < 4; i++) {
            int idx = tid + i * 256;
            int r = idx >> 7, c = idx & 127;
            Bs[0][r][c] = W[(size_t)r * HC + col0 + c];
        }
    }
    __syncthreads();

    const int T = K >> 3;
    for (int kt = 0; kt < T; kt++) {
        const int cur = kt & 1, nxt = cur ^ 1;
        float4 av;
        float bv[4];
        const bool pre = (kt + 1 < T);
        if (pre) {
            const int k0 = (kt + 1) * 8;
            av = make_float4(0.f, 0.f, 0.f, 0.f);
            if (agr < N) av = *(const float4*)(A + (size_t)agr * K + k0 + ac);
            #pragma unroll
            for (int i = 0; i < 4; i++) {
                int idx = tid + i * 256;
                int r = idx >> 7, c = idx & 127;
                bv[i] = W[(size_t)(k0 + r) * HC + col0 + c];
            }
        }
        #pragma unroll
        for (int k = 0; k < 8; k++) {
            float a[8], b[8];
            *(float4*)(a)     = *(const float4*)&As[cur][k][ty * 8];
            *(float4*)(a + 4) = *(const float4*)&As[cur][k][ty * 8 + 4];
            *(float4*)(b)     = *(const float4*)&Bs[cur][k][tx * 8];
            *(float4*)(b + 4) = *(const float4*)&Bs[cur][k][tx * 8 + 4];
            #pragma unroll
            for (int i = 0; i < 8; i++)
                #pragma unroll
                for (int j = 0; j < 8; j++)
                    acc[i][j] = fmaf(a[i], b[j], acc[i][j]);
        }
        if (pre) {
            As[nxt][ac + 0][ar] = av.x; As[nxt][ac + 1][ar] = av.y;
            As[nxt][ac + 2][ar] = av.z; As[nxt][ac + 3][ar] = av.w;
            #pragma unroll
            for (int i = 0; i < 4; i++) {
                int idx = tid + i * 256;
                int r = idx >> 7, c = idx & 127;
                Bs[nxt][r][c] = bv[i];
            }
            __syncthreads();
        }
    }

    #pragma unroll
    for (int i = 0; i < 8; i++) {
        int gr = row0 + ty * 8 + i;
        if (gr >= N) continue;
        #pragma unroll
        for (int j = 0; j < 8; j++) {
            int gc = col0 + tx * 8 + j;
            C[(size_t)gr * HC + gc] = acc[i][j];
        }
    }
}

// ------- fused GATv2 edge phase: fully software-pipelined gather -------
// warp per node; xl[s] for edge p+1 is issued during edge p's compute;
// csr_src/cea prefetched two edges ahead to keep the chain primed.
__global__ void fused_node_kernel(const float* __restrict__ We,
                                  const float* __restrict__ att,
                                  const float* __restrict__ bias,
                                  float* __restrict__ out) {
    const int node = (blockIdx.x * blockDim.x + threadIdx.x) >> 5;
    const int lane = threadIdx.x & 31;
    if (node >= N_NODES) return;

    const int r0 = g_rs[node];
    const int r1 = g_rs[node + 1];

    const float4* W04 = (const float4*)We;
    const float4* W14 = (const float4*)(We + HC);
    const float4* W24 = (const float4*)(We + 2 * HC);
    const float4* At4 = (const float4*)att;

    const float4 w0a = __ldg(&W04[lane]),      w1a = __ldg(&W14[lane]);
    const float4 w2a = __ldg(&W24[lane]),      ata = __ldg(&At4[lane]);
    const float4 w0b = __ldg(&W04[lane + 32]), w1b = __ldg(&W14[lane + 32]);
    const float4 w2b = __ldg(&W24[lane + 32]), atb = __ldg(&At4[lane + 32]);

    const float4* xr4 = (const float4*)(g_xr + (size_t)node * HC);
    const float4 ya = xr4[lane];
    const float4 yb = xr4[lane + 32];

    float mA = -1e30f, mB = -1e30f;
    float sA = 0.f, sB = 0.f;
    float4 accA = make_float4(0.f, 0.f, 0.f, 0.f);
    float4 accB = make_float4(0.f, 0.f, 0.f, 0.f);

    // pipeline state: xa/xb + e_cur hold data for edge p; s_nxt/e_nxt for p+1.
    // every node has >=1 edge (self-loop), so r0 is valid.
    int s0 = g_csr_src[r0];
    float4 e_cur = g_cea[r0];
    const float4* xp = (const float4*)(g_xl + (size_t)s0 * HC);
    float4 xa = xp[lane];
    float4 xb = xp[lane + 32];
    int s_nxt = 0;
    float4 e_nxt = make_float4(0.f, 0.f, 0.f, 0.f);
    if (r0 + 1 < r1) { s_nxt = g_csr_src[r0 + 1]; e_nxt = g_cea[r0 + 1]; }

    for (int p = r0; p < r1; p++) {
        const float4 cxa = xa, cxb = xb, ec = e_cur;

        // rotate pipeline: issue xl gather for edge p+1, prefetch indices for p+2
        if (p + 1 < r1) {
            e_cur = e_nxt;
            const float4* xn = (const float4*)(g_xl + (size_t)s_nxt * HC);
            xa = xn[lane];
            xb = xn[lane + 32];
            if (p + 2 < r1) { s_nxt = g_csr_src[p + 2]; e_nxt = g_cea[p + 2]; }
        }

        float v, pa = 0.f, pb = 0.f;
        v = cxa.x + ya.x + ec.x * w0a.x + ec.y * w1a.x + ec.z * w2a.x; v = v > 0.f ? v : NEG_SLOPE * v; pa += v * ata.x;
        v = cxa.y + ya.y + ec.x * w0a.y + ec.y * w1a.y + ec.z * w2a.y; v = v > 0.f ? v : NEG_SLOPE * v; pa += v * ata.y;
        v = cxa.z + ya.z + ec.x * w0a.z + ec.y * w1a.z + ec.z * w2a.z; v = v > 0.f ? v : NEG_SLOPE * v; pa += v * ata.z;
        v = cxa.w + ya.w + ec.x * w0a.w + ec.y * w1a.w + ec.z * w2a.w; v = v > 0.f ? v : NEG_SLOPE * v; pa += v * ata.w;
        v = cxb.x + yb.x + ec.x * w0b.x + ec.y * w1b.x + ec.z * w2b.x; v = v > 0.f ? v : NEG_SLOPE * v; pb += v * atb.x;
        v = cxb.y + yb.y + ec.x * w0b.y + ec.y * w1b.y + ec.z * w2b.y; v = v > 0.f ? v : NEG_SLOPE * v; pb += v * atb.y;
        v = cxb.z + yb.z + ec.x * w0b.z + ec.y * w1b.z + ec.z * w2b.z; v = v > 0.f ? v : NEG_SLOPE * v; pb += v * atb.z;
        v = cxb.w + yb.w + ec.x * w0b.w + ec.y * w1b.w + ec.z * w2b.w; v = v > 0.f ? v : NEG_SLOPE * v; pb += v * atb.w;

        #pragma unroll
        for (int o = 1; o < 16; o <<= 1) {
            pa += __shfl_xor_sync(0xFFFFFFFFu, pa, o);
            pb += __shfl_xor_sync(0xFFFFFFFFu, pb, o);
        }

        {
            float nm = fmaxf(mA, pa);
            float sc = __expf(mA - nm);
            float w  = __expf(pa - nm);
            sA = sA * sc + w;
            accA.x = accA.x * sc + w * cxa.x;
            accA.y = accA.y * sc + w * cxa.y;
            accA.z = accA.z * sc + w * cxa.z;
            accA.w = accA.w * sc + w * cxa.w;
            mA = nm;
        }
        {
            float nm = fmaxf(mB, pb);
            float sc = __expf(mB - nm);
            float w  = __expf(pb - nm);
            sB = sB * sc + w;
            accB.x = accB.x * sc + w * cxb.x;
            accB.y = accB.y * sc + w * cxb.y;
            accB.z = accB.z * sc + w * cxb.z;
            accB.w = accB.w * sc + w * cxb.w;
            mB = nm;
        }
    }

    const float iA = 1.f / sA;
    const float iB = 1.f / sB;
    float tx = accA.x * iA + accB.x * iB;
    float ty = accA.y * iA + accB.y * iB;
    float tz = accA.z * iA + accB.z * iB;
    float tw = accA.w * iA + accB.w * iB;
    tx += __shfl_xor_sync(0xFFFFFFFFu, tx, 16);
    ty += __shfl_xor_sync(0xFFFFFFFFu, ty, 16);
    tz += __shfl_xor_sync(0xFFFFFFFFu, tz, 16);
    tw += __shfl_xor_sync(0xFFFFFFFFu, tw, 16);
    if (lane < 16) {
        int c = lane * 4;
        float4 bb = *(const float4*)(bias + c);
        float4 o4;
        o4.x = fmaxf(0.25f * tx + bb.x, 0.f);
        o4.y = fmaxf(0.25f * ty + bb.y, 0.f);
        o4.z = fmaxf(0.25f * tz + bb.z, 0.f);
        o4.w = fmaxf(0.25f * tw + bb.w, 0.f);
        *(float4*)(out + (size_t)node * HID + c) = o4;
    }
}

// ---------------- link prediction (warp per original edge) ----------------
__global__ void link_kernel(const int* __restrict__ ei, const float* __restrict__ z,
                            const float* __restrict__ weight, float* __restrict__ link_out) {
    const int warp = (blockIdx.x * blockDim.x + threadIdx.x) >> 5;
    const int lane = threadIdx.x & 31;
    if (warp >= N_EDGES) return;
    int s = ei[warp], d = ei[N_EDGES + warp];
    float v = z[(size_t)s * LAT + lane] * z[(size_t)d * LAT + lane] * weight[lane];
    v = warp_sum(v);
    if (lane == 0) link_out[warp] = v;
}

// ---------------- graph pooling: block per graph (batch is sorted) ----------------
__global__ void pool_kernel(const int* __restrict__ batch, const float* __restrict__ z) {
    const int g = blockIdx.x;
    const int tid = threadIdx.x;
    const int lane = tid & 31;
    const int grp = tid >> 5;   // 8 groups
    __shared__ int s_lo, s_hi;
    __shared__ float red[8][33];
    if (tid == 0) {
        int lo = 0, hi = N_NODES;
        while (lo < hi) { int m = (lo + hi) >> 1; if (batch[m] < g) lo = m + 1; else hi = m; }
        s_lo = lo;
        lo = 0; hi = N_NODES;
        while (lo < hi) { int m = (lo + hi) >> 1; if (batch[m] < g + 1) lo = m + 1; else hi = m; }
        s_hi = lo;
    }
    __syncthreads();
    float acc = 0.f;
    for (int n = s_lo + grp; n < s_hi; n += 8)
        acc += z[(size_t)n * LAT + lane];
    red[grp][lane] = acc;
    __syncthreads();
    if (grp == 0) {
        float v = 0.f;
        #pragma unroll
        for (int k = 0; k < 8; k++) v += red[k][lane];
        g_gemb[g * LAT + lane] = v;
    }
}

// ---------------- classification head ----------------
__global__ void cls_kernel(const float* __restrict__ Wc, const float* __restrict__ bc,
                           float* __restrict__ logits) {
    int i = threadIdx.x;
    if (i >= NGRAPH * NCLS) return;
    int g = i / NCLS, c = i % NCLS;
    float v = bc[c];
    #pragma unroll
    for (int l = 0; l < LAT; l++) v += g_gemb[g * LAT + l] * Wc[l * NCLS + c];
    logits[i] = v;
}

// ---------------- launch ----------------
struct Scratch {
    float* xl; float* xr; float* h;
    int* deg; int* cursor;
    float* easum; float* gemb;
};

static void run_layer(const Scratch& S, const float* X, int in_dim,
                      const float* Wl, const float* Wr,
                      const float* We, const float* att, const float* b,
                      float* out_h) {
    dim3 ggrid(4, (N_NODES + 127) / 128);
    gemm2_kernel<<<ggrid, 256>>>(X, Wl, Wr, S.xl, S.xr, N_NODES, in_dim);
    fused_node_kernel<<<(N_NODES + 7) / 8, 256>>>(We, att, b, out_h);
}

extern "C" void kernel_launch(void* const* d_in, const int* in_sizes, int n_in,
                              void* d_out, int out_size) {
    const float* x     = (const float*)d_in[0];
    const int*   ei    = (const int*)d_in[1];
    const float* ea    = (const float*)d_in[2];
    const int*   batch = (const int*)d_in[3];
    const float* Wl0   = (const float*)d_in[4];
    const float* Wr0   = (const float*)d_in[5];
    const float* We0   = (const float*)d_in[6];
    const float* att0  = (const float*)d_in[7];
    const float* b0    = (const float*)d_in[8];
    const float* Wl1   = (const float*)d_in[9];
    const float* Wr1   = (const float*)d_in[10];
    const float* We1   = (const float*)d_in[11];
    const float* att1  = (const float*)d_in[12];
    const float* b1    = (const float*)d_in[13];
    const float* W_mu  = (const float*)d_in[14];
    const float* b_mu  = (const float*)d_in[15];
    const float* W_dec = (const float*)d_in[16];
    const float* b_dec = (const float*)d_in[17];
    const float* W_cls = (const float*)d_in[18];
    const float* b_cls = (const float*)d_in[19];
    const float* weight= (const float*)d_in[20];

    float* out   = (float*)d_out;
    float* z     = out;                               // [N, 32]
    float* recon = out + (size_t)N_NODES * LAT;       // [N, 128]
    float* link  = recon + (size_t)N_NODES * IN_DIM;  // [E]
    float* logit = link + N_EDGES;                    // [64, 10]

    Scratch S;
    {
        void* p;
        cudaGetSymbolAddress(&p, g_xl);     S.xl     = (float*)p;
        cudaGetSymbolAddress(&p, g_xr);     S.xr     = (float*)p;
        cudaGetSymbolAddress(&p, g_h);      S.h      = (float*)p;
        cudaGetSymbolAddress(&p, g_deg);    S.deg    = (int*)p;
        cudaGetSymbolAddress(&p, g_cursor); S.cursor = (int*)p;
        cudaGetSymbolAddress(&p, g_easum);  S.easum  = (float*)p;
        cudaGetSymbolAddress(&p, g_gemb);   S.gemb   = (float*)p;
    }

    cudaMemsetAsync(S.easum, 0, 3 * sizeof(float));
    cudaMemsetAsync(S.deg, 0, N_NODES * sizeof(int));
    cudaMemsetAsync(S.cursor, 0, N_NODES * sizeof(int));

    ea_sum_kernel<<<256, 256>>>(ea);
    // CSR build (graph static across layers)
    count_kernel<<<(E_TOT + 255) / 256, 256>>>(ei);
    scan_kernel<<<1, 256>>>();
    scatter_kernel<<<(E_TOT + 255) / 256, 256>>>(ei, ea);

    // layer 0: x[N,128] -> h[N,64]
    run_layer(S, x, IN_DIM, Wl0, Wr0, We0, att0, b0, S.h);
    // layer 1: h[N,64] -> h[N,64]
    run_layer(S, S.h, HID, Wl1, Wr1, We1, att1, b1, S.h);

    // z = h @ W_mu + b_mu
    {
        dim3 grid(1, (N_NODES + 127) / 128);
        gemm_kernel<<<grid, 256>>>(S.h, W_mu, b_mu, z, N_NODES, HID, LAT, 0);
    }
    // recon = z @ W_dec + b_dec
    {
        dim3 grid(1, (N_NODES + 127) / 128);
        gemm_kernel<<<grid, 256>>>(z, W_dec, b_dec, recon, N_NODES, LAT, IN_DIM, 0);
    }
    link_kernel<<<(N_EDGES + 7) / 8, 256>>>(ei, z, weight, link);
    pool_kernel<<<NGRAPH, 256>>>(batch, z);
    cls_kernel<<<1, NGRAPH * NCLS>>>(W_cls, b_cls, logit);
}

// round 17
// speedup vs baseline: 1.0900x; 1.0900x over previous
#include <cuda_runtime.h>
#include <cuda_bf16.h>
#include <cstdint>

#define N_NODES 50000
#define N_EDGES 400000
#define E_TOT   (N_EDGES + N_NODES)
#define HEADS   4
#define HID     64
#define HC      256     // HEADS*HID
#define LAT     32
#define IN_DIM  128
#define NGRAPH  64
#define NCLS    10
#define NEG_SLOPE 0.2f
#define DBINS   512

// ---------------- static scratch (no allocations allowed) ----------------
__device__ float    g_xl[(size_t)N_NODES * HC];
__device__ float    g_xr[(size_t)N_NODES * HC];
__device__ float    g_h[(size_t)N_NODES * HID];
__device__ int      g_deg[N_NODES];
__device__ int      g_cursor[N_NODES];
__device__ int      g_rs[N_NODES + 1];               // CSR row starts
__device__ int      g_csr_src[E_TOT];                // src node per CSR slot
__device__ float4   g_cea[E_TOT];                    // edge attr per CSR slot (w unused)
__device__ float    g_easum[3];
__device__ float    g_gemb[NGRAPH * LAT];
__device__ int      g_dhist[DBINS];                  // degree histogram
__device__ int      g_doff[DBINS];                   // descending-degree offsets
__device__ int      g_dcur[DBINS];                   // per-bin cursors
__device__ int      g_perm[N_NODES];                 // nodes sorted by desc degree

__device__ __forceinline__ float warp_sum(float v) {
    #pragma unroll
    for (int o = 16; o > 0; o >>= 1) v += __shfl_xor_sync(0xFFFFFFFFu, v, o);
    return v;
}

// ---------------- edge-attr mean (sums; divided on use) ----------------
__global__ void ea_sum_kernel(const float* __restrict__ ea) {
    float s0 = 0.f, s1 = 0.f, s2 = 0.f;
    for (int i = blockIdx.x * blockDim.x + threadIdx.x; i < N_EDGES;
         i += gridDim.x * blockDim.x) {
        s0 += ea[i * 3 + 0];
        s1 += ea[i * 3 + 1];
        s2 += ea[i * 3 + 2];
    }
    s0 = warp_sum(s0); s1 = warp_sum(s1); s2 = warp_sum(s2);
    if ((threadIdx.x & 31) == 0) {
        atomicAdd(&g_easum[0], s0);
        atomicAdd(&g_easum[1], s1);
        atomicAdd(&g_easum[2], s2);
    }
}

// ---------------- CSR build ----------------
__global__ void count_kernel(const int* __restrict__ ei) {
    int e = blockIdx.x * blockDim.x + threadIdx.x;
    if (e >= E_TOT) return;
    int d = (e < N_EDGES) ? ei[N_EDGES + e] : (e - N_EDGES);
    atomicAdd(&g_deg[d], 1);
}

__global__ void scan_kernel() {
    __shared__ int part[256];
    const int CH = (N_NODES + 255) / 256;
    const int t = threadIdx.x;
    const int start = t * CH;
    int s = 0;
    for (int i = 0; i < CH; i++) {
        int n = start + i;
        if (n < N_NODES) s += g_deg[n];
    }
    part[t] = s;
    __syncthreads();
    for (int o = 1; o < 256; o <<= 1) {
        int u = (t >= o) ? part[t - o] : 0;
        __syncthreads();
        part[t] += u;
        __syncthreads();
    }
    int run = part[t] - s;
    for (int i = 0; i < CH; i++) {
        int n = start + i;
        if (n < N_NODES) { g_rs[n] = run; run += g_deg[n]; }
    }
    if (t == 255) g_rs[N_NODES] = run;
}

__global__ void scatter_kernel(const int* __restrict__ ei, const float* __restrict__ ea) {
    int e = blockIdx.x * blockDim.x + threadIdx.x;
    if (e >= E_TOT) return;
    int s, d;
    float4 c;
    if (e < N_EDGES) {
        s = ei[e]; d = ei[N_EDGES + e];
        c = make_float4(ea[e * 3 + 0], ea[e * 3 + 1], ea[e * 3 + 2], 0.f);
    } else {
        s = d = e - N_EDGES;
        const float inv = 1.0f / (float)N_EDGES;
        c = make_float4(g_easum[0] * inv, g_easum[1] * inv, g_easum[2] * inv, 0.f);
    }
    int pos = g_rs[d] + atomicAdd(&g_cursor[d], 1);
    g_csr_src[pos] = s;
    g_cea[pos] = c;
}

// ---------------- degree sort (counting sort, descending) ----------------
__global__ void deg_hist_kernel() {
    int n = blockIdx.x * blockDim.x + threadIdx.x;
    if (n >= N_NODES) return;
    int d = g_deg[n];
    if (d > DBINS - 1) d = DBINS - 1;
    atomicAdd(&g_dhist[d], 1);
}

// suffix (descending) exclusive scan over DBINS bins; one block of DBINS threads
__global__ void deg_scan_kernel() {
    __shared__ int sh[DBINS];
    const int t = threadIdx.x;
    const int v = g_dhist[t];
    sh[t] = v;
    __syncthreads();
    for (int o = 1; o < DBINS; o <<= 1) {
        int u = (t + o < DBINS) ? sh[t + o] : 0;
        __syncthreads();
        sh[t] += u;
        __syncthreads();
    }
    g_doff[t] = sh[t] - v;   // count of nodes with strictly larger degree bin
}

__global__ void deg_scatter_kernel() {
    int n = blockIdx.x * blockDim.x + threadIdx.x;
    if (n >= N_NODES) return;
    int d = g_deg[n];
    if (d > DBINS - 1) d = DBINS - 1;
    int pos = g_doff[d] + atomicAdd(&g_dcur[d], 1);
    g_perm[pos] = n;
}

// ---------------- SGEMM: C[N,M] = A[N,K] @ W[K,M] (+bias, +relu) ----------------
// 128x128x8 tile, 256 threads, 8x8 microtile, double-buffered smem.
__global__ __launch_bounds__(256, 2)
void gemm_kernel(const float* __restrict__ A, const float* __restrict__ W,
                 const float* __restrict__ bias, float* __restrict__ C,
                 int N, int K, int M, int relu_flag) {
    __shared__ float As[2][8][132];
    __shared__ float Bs[2][8][128];
    const int tid = threadIdx.x;
    const int tx = tid & 15;
    const int ty = tid >> 4;
    const int row0 = blockIdx.y * 128;
    const int col0 = blockIdx.x * 128;
    const int ar  = tid >> 1;
    const int ac  = (tid & 1) * 4;
    const int agr = row0 + ar;

    float acc[8][8];
    #pragma unroll
    for (int i = 0; i < 8; i++)
        #pragma unroll
        for (int j = 0; j < 8; j++) acc[i][j] = 0.f;

    {
        float4 v = make_float4(0.f, 0.f, 0.f, 0.f);
        if (agr < N) v = *(const float4*)(A + (size_t)agr * K + ac);
        As[0][ac + 0][ar] = v.x; As[0][ac + 1][ar] = v.y;
        As[0][ac + 2][ar] = v.z; As[0][ac + 3][ar] = v.w;
        #pragma unroll
        for (int i = 0; i < 4; i++) {
            int idx = tid + i * 256;
            int r = idx >> 7, c = idx & 127;
            int gc = col0 + c;
            Bs[0][r][c] = (gc < M) ? W[(size_t)r * M + gc] : 0.f;
        }
    }
    __syncthreads();

    const int T = K >> 3;
    for (int kt = 0; kt < T; kt++) {
        const int cur = kt & 1, nxt = cur ^ 1;
        float4 av;
        float bv[4];
        const bool pre = (kt + 1 < T);
        if (pre) {
            const int k0 = (kt + 1) * 8;
            av = make_float4(0.f, 0.f, 0.f, 0.f);
            if (agr < N) av = *(const float4*)(A + (size_t)agr * K + k0 + ac);
            #pragma unroll
            for (int i = 0; i < 4; i++) {
                int idx = tid + i * 256;
                int r = idx >> 7, c = idx & 127;
                int gc = col0 + c;
                bv[i] = (gc < M) ? W[(size_t)(k0 + r) * M + gc] : 0.f;
            }
        }
        #pragma unroll
        for (int k = 0; k < 8; k++) {
            float a[8], b[8];
            *(float4*)(a)     = *(const float4*)&As[cur][k][ty * 8];
            *(float4*)(a + 4) = *(const float4*)&As[cur][k][ty * 8 + 4];
            *(float4*)(b)     = *(const float4*)&Bs[cur][k][tx * 8];
            *(float4*)(b + 4) = *(const float4*)&Bs[cur][k][tx * 8 + 4];
            #pragma unroll
            for (int i = 0; i < 8; i++)
                #pragma unroll
                for (int j = 0; j < 8; j++)
                    acc[i][j] = fmaf(a[i], b[j], acc[i][j]);
        }
        if (pre) {
            As[nxt][ac + 0][ar] = av.x; As[nxt][ac + 1][ar] = av.y;
            As[nxt][ac + 2][ar] = av.z; As[nxt][ac + 3][ar] = av.w;
            #pragma unroll
            for (int i = 0; i < 4; i++) {
                int idx = tid + i * 256;
                int r = idx >> 7, c = idx & 127;
                Bs[nxt][r][c] = bv[i];
            }
            __syncthreads();
        }
    }

    #pragma unroll
    for (int i = 0; i < 8; i++) {
        int gr = row0 + ty * 8 + i;
        if (gr >= N) continue;
        #pragma unroll
        for (int j = 0; j < 8; j++) {
            int gc = col0 + tx * 8 + j;
            if (gc >= M) continue;
            float v = acc[i][j];
            if (bias) v += bias[gc];
            if (relu_flag) v = fmaxf(v, 0.f);
            C[(size_t)gr * M + gc] = v;
        }
    }
}

// ---------------- fused dual SGEMM: xl = A@Wl, xr = A@Wr (M=HC=256 each) ----------------
// grid.x = 4: blocks 0-1 -> Wl/Cl cols 0-255, blocks 2-3 -> Wr/Cr cols 0-255.
__global__ __launch_bounds__(256, 2)
void gemm2_kernel(const float* __restrict__ A,
                  const float* __restrict__ Wl, const float* __restrict__ Wr,
                  float* __restrict__ Cl, float* __restrict__ Cr,
                  int N, int K) {
    __shared__ float As[2][8][132];
    __shared__ float Bs[2][8][128];
    const int tid = threadIdx.x;
    const int tx = tid & 15;
    const int ty = tid >> 4;
    const int bx = blockIdx.x;
    const float* W = (bx < 2) ? Wl : Wr;
    float* C       = (bx < 2) ? Cl : Cr;
    const int col0 = (bx & 1) * 128;
    const int row0 = blockIdx.y * 128;
    const int ar  = tid >> 1;
    const int ac  = (tid & 1) * 4;
    const int agr = row0 + ar;

    float acc[8][8];
    #pragma unroll
    for (int i = 0; i < 8; i++)
        #pragma unroll
        for (int j = 0; j < 8; j++) acc[i][j] = 0.f;

    {
        float4 v = make_float4(0.f, 0.f, 0.f, 0.f);
        if (agr < N) v = *(const float4*)(A + (size_t)agr * K + ac);
        As[0][ac + 0][ar] = v.x; As[0][ac + 1][ar] = v.y;
        As[0][ac + 2][ar] = v.z; As[0][ac + 3][ar] = v.w;
        #pragma unroll
        for (int i = 0; i < 4; i++) {
            int idx = tid + i * 256;
            int r = idx >> 7, c = idx & 127;
            Bs[0][r][c] = W[(size_t)r * HC + col0 + c];
        }
    }
    __syncthreads();

    const int T = K >> 3;
    for (int kt = 0; kt < T; kt++) {
        const int cur = kt & 1, nxt = cur ^ 1;
        float4 av;
        float bv[4];
        const bool pre = (kt + 1 < T);
        if (pre) {
            const int k0 = (kt + 1) * 8;
            av = make_float4(0.f, 0.f, 0.f, 0.f);
            if (agr < N) av = *(const float4*)(A + (size_t)agr * K + k0 + ac);
            #pragma unroll
            for (int i = 0; i < 4; i++) {
                int idx = tid + i * 256;
                int r = idx >> 7, c = idx & 127;
                bv[i] = W[(size_t)(k0 + r) * HC + col0 + c];
            }
        }
        #pragma unroll
        for (int k = 0; k < 8; k++) {
            float a[8], b[8];
            *(float4*)(a)     = *(const float4*)&As[cur][k][ty * 8];
            *(float4*)(a + 4) = *(const float4*)&As[cur][k][ty * 8 + 4];
            *(float4*)(b)     = *(const float4*)&Bs[cur][k][tx * 8];
            *(float4*)(b + 4) = *(const float4*)&Bs[cur][k][tx * 8 + 4];
            #pragma unroll
            for (int i = 0; i < 8; i++)
                #pragma unroll
                for (int j = 0; j < 8; j++)
                    acc[i][j] = fmaf(a[i], b[j], acc[i][j]);
        }
        if (pre) {
            As[nxt][ac + 0][ar] = av.x; As[nxt][ac + 1][ar] = av.y;
            As[nxt][ac + 2][ar] = av.z; As[nxt][ac + 3][ar] = av.w;
            #pragma unroll
            for (int i = 0; i < 4; i++) {
                int idx = tid + i * 256;
                int r = idx >> 7, c = idx & 127;
                Bs[nxt][r][c] = bv[i];
            }
            __syncthreads();
        }
    }

    #pragma unroll
    for (int i = 0; i < 8; i++) {
        int gr = row0 + ty * 8 + i;
        if (gr >= N) continue;
        #pragma unroll
        for (int j = 0; j < 8; j++) {
            int gc = col0 + tx * 8 + j;
            C[(size_t)gr * HC + gc] = acc[i][j];
        }
    }
}

// ------- fused GATv2 edge phase (round-15 shape + degree-sorted node order) -------
// warp per node (via g_perm, descending degree); index/attr prefetched one ahead.
__global__ void fused_node_kernel(const float* __restrict__ We,
                                  const float* __restrict__ att,
                                  const float* __restrict__ bias,
                                  float* __restrict__ out) {
    const int wid = (blockIdx.x * blockDim.x + threadIdx.x) >> 5;
    const int lane = threadIdx.x & 31;
    if (wid >= N_NODES) return;
    const int node = g_perm[wid];

    const int r0 = g_rs[node];
    const int r1 = g_rs[node + 1];

    const float4* W04 = (const float4*)We;
    const float4* W14 = (const float4*)(We + HC);
    const float4* W24 = (const float4*)(We + 2 * HC);
    const float4* At4 = (const float4*)att;

    const float4 w0a = __ldg(&W04[lane]),      w1a = __ldg(&W14[lane]);
    const float4 w2a = __ldg(&W24[lane]),      ata = __ldg(&At4[lane]);
    const float4 w0b = __ldg(&W04[lane + 32]), w1b = __ldg(&W14[lane + 32]);
    const float4 w2b = __ldg(&W24[lane + 32]), atb = __ldg(&At4[lane + 32]);

    const float4* xr4 = (const float4*)(g_xr + (size_t)node * HC);
    const float4 ya = xr4[lane];
    const float4 yb = xr4[lane + 32];

    float mA = -1e30f, mB = -1e30f;
    float sA = 0.f, sB = 0.f;
    float4 accA = make_float4(0.f, 0.f, 0.f, 0.f);
    float4 accB = make_float4(0.f, 0.f, 0.f, 0.f);

    // prefetched edge state (every node has >=1 edge: self-loop)
    int s = g_csr_src[r0];
    float4 e = g_cea[r0];

    for (int p = r0; p < r1; p++) {
        const float4* xl4 = (const float4*)(g_xl + (size_t)s * HC);
        const float4 xa = xl4[lane];
        const float4 xb = xl4[lane + 32];
        const float4 ec = e;

        if (p + 1 < r1) {
            s = g_csr_src[p + 1];
            e = g_cea[p + 1];
        }

        float v, pa = 0.f, pb = 0.f;
        v = xa.x + ya.x + ec.x * w0a.x + ec.y * w1a.x + ec.z * w2a.x; v = v > 0.f ? v : NEG_SLOPE * v; pa += v * ata.x;
        v = xa.y + ya.y + ec.x * w0a.y + ec.y * w1a.y + ec.z * w2a.y; v = v > 0.f ? v : NEG_SLOPE * v; pa += v * ata.y;
        v = xa.z + ya.z + ec.x * w0a.z + ec.y * w1a.z + ec.z * w2a.z; v = v > 0.f ? v : NEG_SLOPE * v; pa += v * ata.z;
        v = xa.w + ya.w + ec.x * w0a.w + ec.y * w1a.w + ec.z * w2a.w; v = v > 0.f ? v : NEG_SLOPE * v; pa += v * ata.w;
        v = xb.x + yb.x + ec.x * w0b.x + ec.y * w1b.x + ec.z * w2b.x; v = v > 0.f ? v : NEG_SLOPE * v; pb += v * atb.x;
        v = xb.y + yb.y + ec.x * w0b.y + ec.y * w1b.y + ec.z * w2b.y; v = v > 0.f ? v : NEG_SLOPE * v; pb += v * atb.y;
        v = xb.z + yb.z + ec.x * w0b.z + ec.y * w1b.z + ec.z * w2b.z; v = v > 0.f ? v : NEG_SLOPE * v; pb += v * atb.z;
        v = xb.w + yb.w + ec.x * w0b.w + ec.y * w1b.w + ec.z * w2b.w; v = v > 0.f ? v : NEG_SLOPE * v; pb += v * atb.w;

        #pragma unroll
        for (int o = 1; o < 16; o <<= 1) {
            pa += __shfl_xor_sync(0xFFFFFFFFu, pa, o);
            pb += __shfl_xor_sync(0xFFFFFFFFu, pb, o);
        }

        {
            float nm = fmaxf(mA, pa);
            float sc = __expf(mA - nm);
            float w  = __expf(pa - nm);
            sA = sA * sc + w;
            accA.x = accA.x * sc + w * xa.x;
            accA.y = accA.y * sc + w * xa.y;
            accA.z = accA.z * sc + w * xa.z;
            accA.w = accA.w * sc + w * xa.w;
            mA = nm;
        }
        {
            float nm = fmaxf(mB, pb);
            float sc = __expf(mB - nm);
            float w  = __expf(pb - nm);
            sB = sB * sc + w;
            accB.x = accB.x * sc + w * xb.x;
            accB.y = accB.y * sc + w * xb.y;
            accB.z = accB.z * sc + w * xb.z;
            accB.w = accB.w * sc + w * xb.w;
            mB = nm;
        }
    }

    const float iA = 1.f / sA;
    const float iB = 1.f / sB;
    float tx = accA.x * iA + accB.x * iB;
    float ty = accA.y * iA + accB.y * iB;
    float tz = accA.z * iA + accB.z * iB;
    float tw = accA.w * iA + accB.w * iB;
    tx += __shfl_xor_sync(0xFFFFFFFFu, tx, 16);
    ty += __shfl_xor_sync(0xFFFFFFFFu, ty, 16);
    tz += __shfl_xor_sync(0xFFFFFFFFu, tz, 16);
    tw += __shfl_xor_sync(0xFFFFFFFFu, tw, 16);
    if (lane < 16) {
        int c = lane * 4;
        float4 bb = *(const float4*)(bias + c);
        float4 o4;
        o4.x = fmaxf(0.25f * tx + bb.x, 0.f);
        o4.y = fmaxf(0.25f * ty + bb.y, 0.f);
        o4.z = fmaxf(0.25f * tz + bb.z, 0.f);
        o4.w = fmaxf(0.25f * tw + bb.w, 0.f);
        *(float4*)(out + (size_t)node * HID + c) = o4;
    }
}

// ---------------- link prediction (warp per original edge) ----------------
__global__ void link_kernel(const int* __restrict__ ei, const float* __restrict__ z,
                            const float* __restrict__ weight, float* __restrict__ link_out) {
    const int warp = (blockIdx.x * blockDim.x + threadIdx.x) >> 5;
    const int lane = threadIdx.x & 31;
    if (warp >= N_EDGES) return;
    int s = ei[warp], d = ei[N_EDGES + warp];
    float v = z[(size_t)s * LAT + lane] * z[(size_t)d * LAT + lane] * weight[lane];
    v = warp_sum(v);
    if (lane == 0) link_out[warp] = v;
}

// ---------------- graph pooling: block per graph (batch is sorted) ----------------
__global__ void pool_kernel(const int* __restrict__ batch, const float* __restrict__ z) {
    const int g = blockIdx.x;
    const int tid = threadIdx.x;
    const int lane = tid & 31;
    const int grp = tid >> 5;   // 8 groups
    __shared__ int s_lo, s_hi;
    __shared__ float red[8][33];
    if (tid == 0) {
        int lo = 0, hi = N_NODES;
        while (lo < hi) { int m = (lo + hi) >> 1; if (batch[m] < g) lo = m + 1; else hi = m; }
        s_lo = lo;
        lo = 0; hi = N_NODES;
        while (lo < hi) { int m = (lo + hi) >> 1; if (batch[m] < g + 1) lo = m + 1; else hi = m; }
        s_hi = lo;
    }
    __syncthreads();
    float acc = 0.f;
    for (int n = s_lo + grp; n < s_hi; n += 8)
        acc += z[(size_t)n * LAT + lane];
    red[grp][lane] = acc;
    __syncthreads();
    if (grp == 0) {
        float v = 0.f;
        #pragma unroll
        for (int k = 0; k < 8; k++) v += red[k][lane];
        g_gemb[g * LAT + lane] = v;
    }
}

// ---------------- classification head ----------------
__global__ void cls_kernel(const float* __restrict__ Wc, const float* __restrict__ bc,
                           float* __restrict__ logits) {
    int i = threadIdx.x;
    if (i >= NGRAPH * NCLS) return;
    int g = i / NCLS, c = i % NCLS;
    float v = bc[c];
    #pragma unroll
    for (int l = 0; l < LAT; l++) v += g_gemb[g * LAT + l] * Wc[l * NCLS + c];
    logits[i] = v;
}

// ---------------- launch ----------------
struct Scratch {
    float* xl; float* xr; float* h;
    int* deg; int* cursor;
    float* easum; float* gemb;
    int* dhist; int* dcur;
};

static void run_layer(const Scratch& S, const float* X, int in_dim,
                      const float* Wl, const float* Wr,
                      const float* We, const float* att, const float* b,
                      float* out_h) {
    dim3 ggrid(4, (N_NODES + 127) / 128);
    gemm2_kernel<<<ggrid, 256>>>(X, Wl, Wr, S.xl, S.xr, N_NODES, in_dim);
    fused_node_kernel<<<(N_NODES + 7) / 8, 256>>>(We, att, b, out_h);
}

extern "C" void kernel_launch(void* const* d_in, const int* in_sizes, int n_in,
                              void* d_out, int out_size) {
    const float* x     = (const float*)d_in[0];
    const int*   ei    = (const int*)d_in[1];
    const float* ea    = (const float*)d_in[2];
    const int*   batch = (const int*)d_in[3];
    const float* Wl0   = (const float*)d_in[4];
    const float* Wr0   = (const float*)d_in[5];
    const float* We0   = (const float*)d_in[6];
    const float* att0  = (const float*)d_in[7];
    const float* b0    = (const float*)d_in[8];
    const float* Wl1   = (const float*)d_in[9];
    const float* Wr1   = (const float*)d_in[10];
    const float* We1   = (const float*)d_in[11];
    const float* att1  = (const float*)d_in[12];
    const float* b1    = (const float*)d_in[13];
    const float* W_mu  = (const float*)d_in[14];
    const float* b_mu  = (const float*)d_in[15];
    const float* W_dec = (const float*)d_in[16];
    const float* b_dec = (const float*)d_in[17];
    const float* W_cls = (const float*)d_in[18];
    const float* b_cls = (const float*)d_in[19];
    const float* weight= (const float*)d_in[20];

    float* out   = (float*)d_out;
    float* z     = out;                               // [N, 32]
    float* recon = out + (size_t)N_NODES * LAT;       // [N, 128]
    float* link  = recon + (size_t)N_NODES * IN_DIM;  // [E]
    float* logit = link + N_EDGES;                    // [64, 10]

    Scratch S;
    {
        void* p;
        cudaGetSymbolAddress(&p, g_xl);     S.xl     = (float*)p;
        cudaGetSymbolAddress(&p, g_xr);     S.xr     = (float*)p;
        cudaGetSymbolAddress(&p, g_h);      S.h      = (float*)p;
        cudaGetSymbolAddress(&p, g_deg);    S.deg    = (int*)p;
        cudaGetSymbolAddress(&p, g_cursor); S.cursor = (int*)p;
        cudaGetSymbolAddress(&p, g_easum);  S.easum  = (float*)p;
        cudaGetSymbolAddress(&p, g_gemb);   S.gemb   = (float*)p;
        cudaGetSymbolAddress(&p, g_dhist);  S.dhist  = (int*)p;
        cudaGetSymbolAddress(&p, g_dcur);   S.dcur   = (int*)p;
    }

    cudaMemsetAsync(S.easum, 0, 3 * sizeof(float));
    cudaMemsetAsync(S.deg, 0, N_NODES * sizeof(int));
    cudaMemsetAsync(S.cursor, 0, N_NODES * sizeof(int));
    cudaMemsetAsync(S.dhist, 0, DBINS * sizeof(int));
    cudaMemsetAsync(S.dcur, 0, DBINS * sizeof(int));

    ea_sum_kernel<<<256, 256>>>(ea);
    // CSR build (graph static across layers)
    count_kernel<<<(E_TOT + 255) / 256, 256>>>(ei);
    scan_kernel<<<1, 256>>>();
    scatter_kernel<<<(E_TOT + 255) / 256, 256>>>(ei, ea);
    // degree-descending node permutation (load balance for fused_node)
    deg_hist_kernel<<<(N_NODES + 255) / 256, 256>>>();
    deg_scan_kernel<<<1, DBINS>>>();
    deg_scatter_kernel<<<(N_NODES + 255) / 256, 256>>>();

    // layer 0: x[N,128] -> h[N,64]
    run_layer(S, x, IN_DIM, Wl0, Wr0, We0, att0, b0, S.h);
    // layer 1: h[N,64] -> h[N,64]
    run_layer(S, S.h, HID, Wl1, Wr1, We1, att1, b1, S.h);

    // z = h @ W_mu + b_mu
    {
        dim3 grid(1, (N_NODES + 127) / 128);
        gemm_kernel<<<grid, 256>>>(S.h, W_mu, b_mu, z, N_NODES, HID, LAT, 0);
    }
    // recon = z @ W_dec + b_dec
    {
        dim3 grid(1, (N_NODES + 127) / 128);
        gemm_kernel<<<grid, 256>>>(z, W_dec, b_dec, recon, N_NODES, LAT, IN_DIM, 0);
    }
    link_kernel<<<(N_EDGES + 7) / 8, 256>>>(ei, z, weight, link);
    pool_kernel<<<NGRAPH, 256>>>(batch, z);
    cls_kernel<<<1, NGRAPH * NCLS>>>(W_cls, b_cls, logit);
}